// round 5
// baseline (speedup 1.0000x reference)
#include <cuda_runtime.h>
#include <cstdint>
#include <cstddef>

// Problem constants
#define NROWS 65536   // 64*32*32 flat rows
#define KC    1024    // codes
#define DIM   256     // embedding dim
#define HW    1024    // 32*32

// Output packing (tuple order, all float32)
#define OUT_ZQ   0ull
#define OUT_LOSS 16777216ull
#define OUT_IDX  16777217ull
#define OUT_CB   16842753ull
#define OUT_CS   17104897ull
#define OUT_DW   17105921ull

// Scratch (device globals: no allocations allowed)
__device__ float  g_c2[KC];
__device__ int    g_idx[NROWS];
__device__ int    g_counts[KC];
__device__ float  g_dw[KC * DIM];
__device__ double g_loss;
__device__ int    g_rand[KC];
__device__ float  g_smooth[KC];
__device__ int    g_dead[KC];

// ===========================================================================
__device__ __forceinline__ uint32_t smem_to_u32(const void* p) {
    uint32_t a;
    asm("{ .reg .u64 t; cvta.to.shared.u64 t, %1; cvt.u32.u64 %0, t; }"
        : "=r"(a) : "l"(p));
    return a;
}
#define CP_ASYNC16(dst, src) \
    asm volatile("cp.async.ca.shared.global [%0], [%1], 16;" :: "r"(dst), "l"(src))
#define CP_COMMIT()  asm volatile("cp.async.commit_group;" ::: "memory")
#define CP_WAIT1()   asm volatile("cp.async.wait_group 1;" ::: "memory")
#define CP_WAIT0()   asm volatile("cp.async.wait_group 0;" ::: "memory")
#define LDSM_X4(r0, r1, r2, r3, addr) \
    asm volatile("ldmatrix.sync.aligned.m8n8.x4.shared.b16 {%0,%1,%2,%3}, [%4];" \
                 : "=r"(r0), "=r"(r1), "=r"(r2), "=r"(r3) : "r"(addr))
#define MMA_TF32(d, a0, a1, a2, a3, b0, b1) \
    asm volatile("mma.sync.aligned.m16n8k8.row.col.f32.tf32.tf32.f32 " \
                 "{%0,%1,%2,%3}, {%4,%5,%6,%7}, {%8,%9}, {%0,%1,%2,%3};" \
                 : "+f"((d)[0]), "+f"((d)[1]), "+f"((d)[2]), "+f"((d)[3]) \
                 : "r"(a0), "r"(a1), "r"(a2), "r"(a3), "r"(b0), "r"(b1))

// ===========================================================================
__global__ void k_init() {
    int i = blockIdx.x * blockDim.x + threadIdx.x;
    if (i < KC * DIM) g_dw[i] = 0.0f;
    if (i < KC)       g_counts[i] = 0;
    if (i == 0)       g_loss = 0.0;
}

// c2[k] = sum_d fl(cb[k][d]^2), sequential in-order fp32 (XLA CPU naive reduce)
__global__ void k_c2(const float* __restrict__ cb) {
    int k = blockIdx.x * blockDim.x + threadIdx.x;
    if (k >= KC) return;
    const float* row = cb + (size_t)k * DIM;
    float s = 0.0f;
    for (int d = 0; d < DIM; ++d) {
        float v = row[d];
        s = __fadd_rn(s, __fmul_rn(v, v));
    }
    g_c2[k] = s;
}

// Exact JAX threefry2x32 for key(1)
__device__ __forceinline__ uint32_t tf_rotl(uint32_t v, int r) {
    return (v << r) | (v >> (32 - r));
}
__global__ void k_rng() {
    int i = threadIdx.x;
    if (i >= 512) return;
    const uint32_t ks0 = 0u, ks1 = 1u, ks2 = 0x1BD11BDBu;
    uint32_t x0 = (uint32_t)i + ks0;
    uint32_t x1 = (uint32_t)(i + 512) + ks1;
    const int ra[4] = {13, 15, 26, 6};
    const int rb[4] = {17, 29, 16, 24};
#define TF_R4(rots) { x0 += x1; x1 = tf_rotl(x1, rots[0]); x1 ^= x0; \
                      x0 += x1; x1 = tf_rotl(x1, rots[1]); x1 ^= x0; \
                      x0 += x1; x1 = tf_rotl(x1, rots[2]); x1 ^= x0; \
                      x0 += x1; x1 = tf_rotl(x1, rots[3]); x1 ^= x0; }
    TF_R4(ra); x0 += ks1; x1 += ks2 + 1u;
    TF_R4(rb); x0 += ks2; x1 += ks0 + 2u;
    TF_R4(ra); x0 += ks0; x1 += ks1 + 3u;
    TF_R4(rb); x0 += ks1; x1 += ks2 + 4u;
    TF_R4(ra); x0 += ks2; x1 += ks0 + 5u;
#undef TF_R4
    g_rand[i]       = (int)(x0 & 0xFFFFu);
    g_rand[i + 512] = (int)(x1 & 0xFFFFu);
}

// ===========================================================================
// Tensor-core (mma.sync tf32) filter + exact sequential-fp32-chain recheck.
// CTA = 128 rows, 256 threads (8 warps, 16 rows each), grid 512.
//
// SMEM (floats):
//   s_A   [128][260]            = 33280   (A tile, stride 260 -> LDSM conflict-free)
//   s_B   2 x [32][260]         = 16640   (code chunk, double buffered)
//   s_c2  [1024]
//   s_rmin[128], s_cnt[128], s_slot[128*16]
#define AF      33280
#define BF      16640
#define BCHUNKB (32 * 260 * 4)      // bytes per B buffer = 33280
#define SMEM_TC ((AF + BF + 1024 + 128 + 128 + 2048) * 4)
#define MARGIN  5e-3f

__device__ __forceinline__ void stage_chunk(const float* __restrict__ cb,
                                            uint32_t uBuf, int chunk, int tid) {
    const float* src0 = cb + (size_t)(chunk * 32) * DIM;
#pragma unroll
    for (int i = 0; i < 8; ++i) {
        int s = tid + 256 * i;          // 0..2047
        int code = s >> 6, seg = s & 63;
        const float* src = src0 + code * DIM + seg * 4;
        uint32_t dst = uBuf + (uint32_t)(code * 260 + seg * 4) * 4;
        CP_ASYNC16(dst, src);
    }
    CP_COMMIT();
}

__global__ void __launch_bounds__(256) k_argmin_tc(const float* __restrict__ z,
                                                   const float* __restrict__ cb) {
    extern __shared__ float smf[];
    float* s_A    = smf;
    float* s_B    = smf + AF;
    float* s_c2   = smf + AF + BF;
    float* s_rmin = s_c2 + KC;
    int*   s_cnt  = (int*)(s_rmin + 128);
    int*   s_slot = s_cnt + 128;

    const uint32_t uA = smem_to_u32(smf);
    const uint32_t uB = uA + AF * 4;

    const int tid = threadIdx.x, lane = tid & 31, wid = tid >> 5;
    const int warpRow = wid * 16;

    for (int i = tid; i < KC; i += 256) s_c2[i] = g_c2[i];
    if (tid < 128) { s_rmin[tid] = 3.4e38f; s_cnt[tid] = 0; }

    const int n0 = blockIdx.x * 128;
    const int b = n0 >> 10, hw0 = n0 & 1023;
    const float* zb = z + (size_t)b * (DIM * HW) + hw0;

    // ---- stage A: rows 0..127, dims 0..255, stride 260
    {
        int row = tid & 127, half = tid >> 7;
        for (int i = 0; i < 128; ++i) {
            int d = i * 2 + half;
            s_A[row * 260 + d] = zb[(size_t)d * HW + row];
        }
    }
    __syncthreads();

    // ldmatrix lane address precompute
    const int aRow = warpRow + (lane & 15);
    const int aCol = (lane >> 2) & 4;              // +4 for lanes 16..31
    const uint32_t aBase = uA + (uint32_t)(aRow * 260 + aCol) * 4;
    const int bN   = (lane & 7) + ((lane & 16) >> 1);   // +8 for lanes 16..31
    const int bCol = (lane & 8) >> 1;                   // +4 for lanes 8..15
    const uint32_t bRel = (uint32_t)(bN * 260 + bCol) * 4;

    const int rLo = warpRow + (lane >> 2);
    const int rHi = rLo + 8;

    for (int pass = 0; pass < 2; ++pass) {
        float minLo = 3.4e38f, minHi = 3.4e38f;
        float thrLo = 0.0f, thrHi = 0.0f;
        if (pass == 1) {
            thrLo = s_rmin[rLo] + MARGIN;
            thrHi = s_rmin[rHi] + MARGIN;
        }
        stage_chunk(cb, uB, 0, tid);

        for (int c = 0; c < 32; ++c) {
            if (c < 31) { stage_chunk(cb, uB + ((c + 1) & 1) * BCHUNKB, c + 1, tid); CP_WAIT1(); }
            else        { CP_WAIT0(); }
            __syncthreads();

            const uint32_t bufU = uB + (c & 1) * BCHUNKB;
            float acc[4][4];
#pragma unroll
            for (int t = 0; t < 4; ++t)
#pragma unroll
                for (int j = 0; j < 4; ++j) acc[t][j] = 0.0f;

#pragma unroll 4
            for (int step = 0; step < 32; ++step) {
                uint32_t a0, a1, a2, a3, p0, p1, p2, p3, q0, q1, q2, q3;
                LDSM_X4(a0, a1, a2, a3, aBase + step * 32);
                LDSM_X4(p0, p1, p2, p3, bufU + bRel + step * 32);
                LDSM_X4(q0, q1, q2, q3, bufU + bRel + 16 * 260 * 4 + step * 32);
                MMA_TF32(acc[0], a0, a1, a2, a3, p0, p1);
                MMA_TF32(acc[1], a0, a1, a2, a3, p2, p3);
                MMA_TF32(acc[2], a0, a1, a2, a3, q0, q1);
                MMA_TF32(acc[3], a0, a1, a2, a3, q2, q3);
            }

            // epilogue: s = c2[k] - 2*dot
            int cbase = c * 32;
#pragma unroll
            for (int t = 0; t < 4; ++t) {
                int kb = cbase + t * 8 + 2 * (lane & 3);
                float c2a = s_c2[kb], c2b = s_c2[kb + 1];
                float s0 = fmaf(-2.0f, acc[t][0], c2a);
                float s1 = fmaf(-2.0f, acc[t][1], c2b);
                float s2 = fmaf(-2.0f, acc[t][2], c2a);
                float s3 = fmaf(-2.0f, acc[t][3], c2b);
                if (pass == 0) {
                    minLo = fminf(minLo, fminf(s0, s1));
                    minHi = fminf(minHi, fminf(s2, s3));
                } else {
                    if (s0 <= thrLo) { int p = atomicAdd(&s_cnt[rLo], 1); if (p < 16) s_slot[rLo * 16 + p] = kb; }
                    if (s1 <= thrLo) { int p = atomicAdd(&s_cnt[rLo], 1); if (p < 16) s_slot[rLo * 16 + p] = kb + 1; }
                    if (s2 <= thrHi) { int p = atomicAdd(&s_cnt[rHi], 1); if (p < 16) s_slot[rHi * 16 + p] = kb; }
                    if (s3 <= thrHi) { int p = atomicAdd(&s_cnt[rHi], 1); if (p < 16) s_slot[rHi * 16 + p] = kb + 1; }
                }
            }
            __syncthreads();
        }

        if (pass == 0) {
            // reduce across the 4 lanes sharing each row
#pragma unroll
            for (int off = 1; off < 4; off <<= 1) {
                minLo = fminf(minLo, __shfl_xor_sync(0xffffffffu, minLo, off));
                minHi = fminf(minHi, __shfl_xor_sync(0xffffffffu, minHi, off));
            }
            if ((lane & 3) == 0) { s_rmin[rLo] = minLo; s_rmin[rHi] = minHi; }
        }
        __syncthreads();
    }

    // ---- exact recheck: bitwise sequential fp32 chains for candidates
    if (tid < 128) {
        int r = tid;
        int cN = s_cnt[r];
        float best = 3.4e38f; int bk = 1 << 30;
        float f2 = 0.0f;
        if (cN <= 16) {
            for (int g0 = 0; g0 < cN; g0 += 4) {
                int m = cN - g0; if (m > 4) m = 4;
                int kk[4]; float acc[4];
#pragma unroll
                for (int j = 0; j < 4; ++j) {
                    kk[j] = s_slot[r * 16 + g0 + (j < m ? j : 0)];
                    acc[j] = 0.0f;
                }
                float f2a = 0.0f;
                const float* c0 = cb + (size_t)kk[0] * DIM;
                const float* c1 = cb + (size_t)kk[1] * DIM;
                const float* c2p = cb + (size_t)kk[2] * DIM;
                const float* c3 = cb + (size_t)kk[3] * DIM;
                for (int d = 0; d < DIM; ++d) {
                    float fv = zb[(size_t)d * HW + r];
                    if (g0 == 0) f2a = __fadd_rn(f2a, __fmul_rn(fv, fv));
                    acc[0] = __fmaf_rn(fv, c0[d], acc[0]);
                    acc[1] = __fmaf_rn(fv, c1[d], acc[1]);
                    acc[2] = __fmaf_rn(fv, c2p[d], acc[2]);
                    acc[3] = __fmaf_rn(fv, c3[d], acc[3]);
                }
                if (g0 == 0) f2 = f2a;
                for (int j = 0; j < m; ++j) {
                    float d2 = __fadd_rn(__fsub_rn(f2, 2.0f * acc[j]), s_c2[kk[j]]);
                    int k = kk[j];
                    if (d2 < best || (d2 == best && k < bk)) { best = d2; bk = k; }
                }
            }
        } else {
            // overflow fallback: exact full scan (astronomically rare)
            for (int g0 = 0; g0 < KC; g0 += 4) {
                float acc[4] = {0.f, 0.f, 0.f, 0.f};
                float f2a = 0.0f;
                const float* cp = cb + (size_t)g0 * DIM;
                for (int d = 0; d < DIM; ++d) {
                    float fv = zb[(size_t)d * HW + r];
                    if (g0 == 0) f2a = __fadd_rn(f2a, __fmul_rn(fv, fv));
                    acc[0] = __fmaf_rn(fv, cp[d], acc[0]);
                    acc[1] = __fmaf_rn(fv, cp[DIM + d], acc[1]);
                    acc[2] = __fmaf_rn(fv, cp[2 * DIM + d], acc[2]);
                    acc[3] = __fmaf_rn(fv, cp[3 * DIM + d], acc[3]);
                }
                if (g0 == 0) f2 = f2a;
                for (int j = 0; j < 4; ++j) {
                    float d2 = __fadd_rn(__fsub_rn(f2, 2.0f * acc[j]), s_c2[g0 + j]);
                    int k = g0 + j;
                    if (d2 < best || (d2 == best && k < bk)) { best = d2; bk = k; }
                }
            }
        }
        g_idx[n0 + r] = bk;
        atomicAdd(&g_counts[bk], 1);
    }
}

// ===========================================================================
__global__ void __launch_bounds__(256) k_scatter(const float* __restrict__ z,
                                                 const float* __restrict__ cb,
                                                 float* __restrict__ out,
                                                 size_t osz) {
    int n  = blockIdx.x * 256 + threadIdx.x;
    int b  = n >> 10, hw = n & 1023;
    int k  = g_idx[n];
    if (OUT_IDX + (size_t)n < osz) out[OUT_IDX + n] = (float)k;

    const float*  zr   = z  + (size_t)b * DIM * HW + hw;
    float*        orow = out + OUT_ZQ + (size_t)b * DIM * HW + hw;
    const float4* cr   = (const float4*)(cb + (size_t)k * DIM);
    float*        dwr  = g_dw + (size_t)k * DIM;

    float ls = 0.0f;
#pragma unroll 4
    for (int d4 = 0; d4 < 64; ++d4) {
        float4 qv = cr[d4];
        int d = d4 * 4;
        float z0 = zr[(size_t)(d + 0) * HW];
        float z1 = zr[(size_t)(d + 1) * HW];
        float z2 = zr[(size_t)(d + 2) * HW];
        float z3 = zr[(size_t)(d + 3) * HW];
        orow[(size_t)(d + 0) * HW] = qv.x;
        orow[(size_t)(d + 1) * HW] = qv.y;
        orow[(size_t)(d + 2) * HW] = qv.z;
        orow[(size_t)(d + 3) * HW] = qv.w;
        float e0 = qv.x - z0, e1 = qv.y - z1, e2 = qv.z - z2, e3 = qv.w - z3;
        ls = fmaf(e0, e0, ls); ls = fmaf(e1, e1, ls);
        ls = fmaf(e2, e2, ls); ls = fmaf(e3, e3, ls);
        atomicAdd(&dwr[d + 0], z0);
        atomicAdd(&dwr[d + 1], z1);
        atomicAdd(&dwr[d + 2], z2);
        atomicAdd(&dwr[d + 3], z3);
    }

    for (int o = 16; o > 0; o >>= 1) ls += __shfl_down_sync(0xffffffffu, ls, o);
    __shared__ float ws[8];
    int lane = threadIdx.x & 31, w = threadIdx.x >> 5;
    if (lane == 0) ws[w] = ls;
    __syncthreads();
    if (threadIdx.x == 0) {
        float s = 0.0f;
#pragma unroll
        for (int i = 0; i < 8; ++i) s += ws[i];
        atomicAdd(&g_loss, (double)s);
    }
}

// ===========================================================================
__global__ void k_fin_a(const float* __restrict__ ema_cs,
                        float* __restrict__ out, size_t osz) {
    int k = threadIdx.x;
    float cs = __fadd_rn(__fmul_rn(0.99f, ema_cs[k]),
                         __fmul_rn(0.01f, (float)g_counts[k]));
    __shared__ float red[1024];
    red[k] = cs;
    __syncthreads();
    for (int o = 512; o > 0; o >>= 1) {
        if (k < o) red[k] += red[k + o];
        __syncthreads();
    }
    float n = red[0];
    float smv = (cs + 1e-5f) / (n + 1024.0f * 1e-5f) * n;
    g_smooth[k] = smv;
    int dead = cs < 1.0f;
    g_dead[k] = dead;
    if (OUT_CS + (size_t)k < osz) out[OUT_CS + k] = dead ? 1.0f : cs;
    if (k == 0 && OUT_LOSS < osz)
        out[OUT_LOSS] = (float)(0.5 * g_loss / 16777216.0);
}

// ===========================================================================
__global__ void k_fin_b(const float* __restrict__ ema_dw,
                        const float* __restrict__ z,
                        float* __restrict__ out, size_t osz) {
    int k = blockIdx.x;
    int d = threadIdx.x;
    size_t e = (size_t)k * DIM + d;
    float dwe = __fadd_rn(__fmul_rn(0.99f, ema_dw[e]),
                          __fmul_rn(0.01f, g_dw[e]));
    float cbv = dwe / g_smooth[k];
    if (g_dead[k]) {
        int r = g_rand[k];
        int rb = r >> 10, rhw = r & 1023;
        float rr = z[((size_t)rb * DIM + d) * HW + rhw];
        cbv = rr;
        dwe = rr;
    }
    if (OUT_CB + e < osz) out[OUT_CB + e] = cbv;
    if (OUT_DW + e < osz) out[OUT_DW + e] = dwe;
}

// ===========================================================================
extern "C" void kernel_launch(void* const* d_in, const int* in_sizes, int n_in,
                              void* d_out, int out_size) {
    const float* z      = (const float*)d_in[0];
    const float* cb     = (const float*)d_in[1];
    const float* ema_cs = (const float*)d_in[2];
    const float* ema_dw = (const float*)d_in[3];
    float* out = (float*)d_out;
    size_t osz = (size_t)out_size;

    cudaFuncSetAttribute(k_argmin_tc, cudaFuncAttributeMaxDynamicSharedMemorySize,
                         SMEM_TC);

    k_init<<<1024, 256>>>();
    k_c2<<<4, 256>>>(cb);
    k_rng<<<1, 512>>>();
    k_argmin_tc<<<512, 256, SMEM_TC>>>(z, cb);
    k_scatter<<<256, 256>>>(z, cb, out, osz);
    k_fin_a<<<1, 1024>>>(ema_cs, out, osz);
    k_fin_b<<<1024, 256>>>(ema_dw, z, out, osz);
}

// round 6
// speedup vs baseline: 1.1003x; 1.1003x over previous
#include <cuda_runtime.h>
#include <cuda_fp16.h>
#include <cstdint>
#include <cstddef>

// Problem constants
#define NROWS 65536   // 64*32*32 flat rows
#define KC    1024    // codes
#define DIM   256     // embedding dim
#define HW    1024    // 32*32

// Output packing (tuple order, all float32)
#define OUT_ZQ   0ull
#define OUT_LOSS 16777216ull
#define OUT_IDX  16777217ull
#define OUT_CB   16842753ull
#define OUT_CS   17104897ull
#define OUT_DW   17105921ull

#define NSLOT  48
#define MARGIN 1.2e-2f

// Scratch (device globals: no allocations allowed)
__device__ float  g_c2[KC];
__device__ int    g_idx[NROWS];
__device__ int    g_counts[KC];
__device__ float  g_dw[KC * DIM];
__device__ double g_loss;
__device__ int    g_rand[KC];
__device__ float  g_smooth[KC];
__device__ int    g_dead[KC];
__device__ float  g_scores[(size_t)NROWS * KC];   // 256 MB approx scores
__device__ float  g_rmin[NROWS];
__device__ int    g_ccnt[NROWS];
__device__ int    g_cand[NROWS * NSLOT];

// ===========================================================================
__global__ void k_init() {
    int i = blockIdx.x * blockDim.x + threadIdx.x;   // 262144
    if (i < KC * DIM) g_dw[i] = 0.0f;
    if (i < KC)       g_counts[i] = 0;
    if (i < NROWS)    g_ccnt[i] = 0;
    if (i == 0)       g_loss = 0.0;
}

// c2[k] = sum_d fl(cb[k][d]^2), sequential in-order fp32 (XLA CPU naive reduce)
__global__ void k_c2(const float* __restrict__ cb) {
    int k = blockIdx.x * blockDim.x + threadIdx.x;
    if (k >= KC) return;
    const float* row = cb + (size_t)k * DIM;
    float s = 0.0f;
    for (int d = 0; d < DIM; ++d) {
        float v = row[d];
        s = __fadd_rn(s, __fmul_rn(v, v));
    }
    g_c2[k] = s;
}

// Exact JAX threefry2x32 for key(1)
__device__ __forceinline__ uint32_t tf_rotl(uint32_t v, int r) {
    return (v << r) | (v >> (32 - r));
}
__global__ void k_rng() {
    int i = threadIdx.x;
    if (i >= 512) return;
    const uint32_t ks0 = 0u, ks1 = 1u, ks2 = 0x1BD11BDBu;
    uint32_t x0 = (uint32_t)i + ks0;
    uint32_t x1 = (uint32_t)(i + 512) + ks1;
    const int ra[4] = {13, 15, 26, 6};
    const int rb[4] = {17, 29, 16, 24};
#define TF_R4(rots) { x0 += x1; x1 = tf_rotl(x1, rots[0]); x1 ^= x0; \
                      x0 += x1; x1 = tf_rotl(x1, rots[1]); x1 ^= x0; \
                      x0 += x1; x1 = tf_rotl(x1, rots[2]); x1 ^= x0; \
                      x0 += x1; x1 = tf_rotl(x1, rots[3]); x1 ^= x0; }
    TF_R4(ra); x0 += ks1; x1 += ks2 + 1u;
    TF_R4(rb); x0 += ks2; x1 += ks0 + 2u;
    TF_R4(ra); x0 += ks0; x1 += ks1 + 3u;
    TF_R4(rb); x0 += ks1; x1 += ks2 + 4u;
    TF_R4(ra); x0 += ks2; x1 += ks0 + 5u;
#undef TF_R4
    g_rand[i]       = (int)(x0 & 0xFFFFu);
    g_rand[i + 512] = (int)(x1 & 0xFFFFu);
}

// ===========================================================================
// k_filter: fp16 HFMA2 approx GEMM. CTA = 32 rows, 256 threads, 2048 CTAs.
// Writes g_scores[n][k] (fp32) and per-row min g_rmin[n].
// smem: s_flat half2[128 d2][32 rows] = 16384 B
//       s_code half2[128 d2][72]      = 36864 B (stride 72, 64 codes used)
//       s_c2   float [1024]           =  4096 B
#define SM_FLAT_B 16384
#define SM_CODE_B 36864
#define SMEM_FILT (SM_FLAT_B + SM_CODE_B + 4096)

__global__ void __launch_bounds__(256) k_filter(const float* __restrict__ z,
                                                const float* __restrict__ cb) {
    extern __shared__ char smraw[];
    __half*  s_flat_h  = (__half*)smraw;
    __half2* s_flat_h2 = (__half2*)smraw;
    __half2* s_code_h2 = (__half2*)(smraw + SM_FLAT_B);
    float*   s_c2      = (float*)(smraw + SM_FLAT_B + SM_CODE_B);

    const int tid = threadIdx.x;
    const int g = tid & 15;        // code-group: codes 4g..4g+3 of tile
    const int q = tid >> 4;        // row-group : rows 2q, 2q+1

    for (int i = tid; i < KC; i += 256) s_c2[i] = g_c2[i];

    const int n0 = blockIdx.x * 32;
    const int b = n0 >> 10, hw0 = n0 & 1023;
    const float* zb = z + (size_t)b * (DIM * HW) + hw0;

    // ---- stage flat tile: half at [d2][r] (r*2 + (d&1))
    {
        int r = tid & 31, dchunk = tid >> 5;         // 8 chunks x 32 dims
#pragma unroll
        for (int i = 0; i < 32; ++i) {
            int d = dchunk * 32 + i;
            float v = zb[(size_t)d * HW + r];
            s_flat_h[(d >> 1) * 64 + r * 2 + (d & 1)] = __float2half(v);
        }
    }

    float runmin0 = 3.4e38f, runmin1 = 3.4e38f;

    for (int t = 0; t < 16; ++t) {
        __syncthreads();
        // ---- stage 64-code tile: half2 (dims d0,d0+1) at [d0/2][code]
        {
            int code = tid >> 2, dseg = tid & 3;
            const float* src = cb + (size_t)(t * 64 + code) * DIM;
#pragma unroll
            for (int j = 0; j < 16; ++j) {
                int d0 = 4 * dseg + 16 * j;          // multiple of 4
                float4 v = *(const float4*)(src + d0);
                int d2a = d0 >> 1;
                s_code_h2[d2a * 72 + code] = __floats2half2_rn(v.x, v.y);
                s_code_h2[(d2a + 1) * 72 + code] = __floats2half2_rn(v.z, v.w);
            }
        }
        __syncthreads();

        float facc[2][4];
#pragma unroll
        for (int a = 0; a < 2; ++a)
#pragma unroll
            for (int c = 0; c < 4; ++c) facc[a][c] = 0.0f;

        // 4 chunks of 32 d2 (64 dims): h2 accumulate, flush to fp32
        for (int ch = 0; ch < 4; ++ch) {
            __half2 acc[2][4];
#pragma unroll
            for (int a = 0; a < 2; ++a)
#pragma unroll
                for (int c = 0; c < 4; ++c) acc[a][c] = __float2half2_rn(0.0f);
#pragma unroll 8
            for (int i = 0; i < 32; ++i) {
                int d2 = ch * 32 + i;
                float2 faf = *(const float2*)(s_flat_h2 + d2 * 32 + 2 * q);
                float4 ccf = *(const float4*)(s_code_h2 + d2 * 72 + 4 * g);
                __half2 fa0 = *(__half2*)&faf.x;
                __half2 fa1 = *(__half2*)&faf.y;
                __half2 c0 = *(__half2*)&ccf.x;
                __half2 c1 = *(__half2*)&ccf.y;
                __half2 c2v = *(__half2*)&ccf.z;
                __half2 c3 = *(__half2*)&ccf.w;
                acc[0][0] = __hfma2(fa0, c0, acc[0][0]);
                acc[0][1] = __hfma2(fa0, c1, acc[0][1]);
                acc[0][2] = __hfma2(fa0, c2v, acc[0][2]);
                acc[0][3] = __hfma2(fa0, c3, acc[0][3]);
                acc[1][0] = __hfma2(fa1, c0, acc[1][0]);
                acc[1][1] = __hfma2(fa1, c1, acc[1][1]);
                acc[1][2] = __hfma2(fa1, c2v, acc[1][2]);
                acc[1][3] = __hfma2(fa1, c3, acc[1][3]);
            }
#pragma unroll
            for (int a = 0; a < 2; ++a)
#pragma unroll
                for (int c = 0; c < 4; ++c) {
                    float2 tv = __half22float2(acc[a][c]);
                    facc[a][c] += tv.x + tv.y;
                }
        }

        // ---- epilogue: s = c2[k] - 2*dot ; track min; store scores
        int kb = t * 64 + 4 * g;
#pragma unroll
        for (int a = 0; a < 2; ++a) {
            float s0 = fmaf(-2.0f, facc[a][0], s_c2[kb + 0]);
            float s1 = fmaf(-2.0f, facc[a][1], s_c2[kb + 1]);
            float s2 = fmaf(-2.0f, facc[a][2], s_c2[kb + 2]);
            float s3 = fmaf(-2.0f, facc[a][3], s_c2[kb + 3]);
            float m = fminf(fminf(s0, s1), fminf(s2, s3));
            if (a == 0) runmin0 = fminf(runmin0, m);
            else        runmin1 = fminf(runmin1, m);
            *(float4*)&g_scores[(size_t)(n0 + 2 * q + a) * KC + kb] =
                make_float4(s0, s1, s2, s3);
        }
    }

    // reduce mins over the 16 g-lanes (same q within half-warp)
#pragma unroll
    for (int off = 1; off < 16; off <<= 1) {
        runmin0 = fminf(runmin0, __shfl_xor_sync(0xffffffffu, runmin0, off));
        runmin1 = fminf(runmin1, __shfl_xor_sync(0xffffffffu, runmin1, off));
    }
    if (g == 0) {
        g_rmin[n0 + 2 * q]     = runmin0;
        g_rmin[n0 + 2 * q + 1] = runmin1;
    }
}

// ===========================================================================
// k_cand: scan scores, collect candidates within margin of row min.
__global__ void __launch_bounds__(256) k_cand() {
    int wid = threadIdx.x >> 5, lane = threadIdx.x & 31;
    int rbase = blockIdx.x * 32 + wid * 4;     // 2048 blocks, 4 rows per warp
#pragma unroll
    for (int r4 = 0; r4 < 4; ++r4) {
        int row = rbase + r4;
        float thr = g_rmin[row] + MARGIN;
        const float* sr = &g_scores[(size_t)row * KC];
#pragma unroll
        for (int i = 0; i < 8; ++i) {
            int k0 = i * 128 + lane * 4;
            float4 v = *(const float4*)(sr + k0);
            if (v.x <= thr) { int p = atomicAdd(&g_ccnt[row], 1); if (p < NSLOT) g_cand[row * NSLOT + p] = k0; }
            if (v.y <= thr) { int p = atomicAdd(&g_ccnt[row], 1); if (p < NSLOT) g_cand[row * NSLOT + p] = k0 + 1; }
            if (v.z <= thr) { int p = atomicAdd(&g_ccnt[row], 1); if (p < NSLOT) g_cand[row * NSLOT + p] = k0 + 2; }
            if (v.w <= thr) { int p = atomicAdd(&g_ccnt[row], 1); if (p < NSLOT) g_cand[row * NSLOT + p] = k0 + 3; }
        }
    }
}

// ===========================================================================
// k_exact: bitwise sequential fp32 chains for candidates; tie -> lowest k.
__global__ void __launch_bounds__(256) k_exact(const float* __restrict__ z,
                                               const float* __restrict__ cb) {
    int n = blockIdx.x * 256 + threadIdx.x;
    int b = n >> 10, r = n & 1023;
    const float* zb = z + (size_t)b * (DIM * HW);
    int cN = g_ccnt[n];
    float best = 3.4e38f; int bk = 1 << 30;
    float f2 = 0.0f;
    if (cN <= NSLOT) {
        for (int g0 = 0; g0 < cN; g0 += 4) {
            int m = cN - g0; if (m > 4) m = 4;
            int kk[4]; float acc[4];
#pragma unroll
            for (int j = 0; j < 4; ++j) {
                kk[j] = g_cand[n * NSLOT + g0 + (j < m ? j : 0)];
                acc[j] = 0.0f;
            }
            float f2a = 0.0f;
            const float* c0 = cb + (size_t)kk[0] * DIM;
            const float* c1 = cb + (size_t)kk[1] * DIM;
            const float* c2p = cb + (size_t)kk[2] * DIM;
            const float* c3 = cb + (size_t)kk[3] * DIM;
            for (int d = 0; d < DIM; ++d) {
                float fv = zb[(size_t)d * HW + r];
                if (g0 == 0) f2a = __fadd_rn(f2a, __fmul_rn(fv, fv));
                acc[0] = __fmaf_rn(fv, c0[d], acc[0]);
                acc[1] = __fmaf_rn(fv, c1[d], acc[1]);
                acc[2] = __fmaf_rn(fv, c2p[d], acc[2]);
                acc[3] = __fmaf_rn(fv, c3[d], acc[3]);
            }
            if (g0 == 0) f2 = f2a;
            for (int j = 0; j < m; ++j) {
                float d2 = __fadd_rn(__fsub_rn(f2, 2.0f * acc[j]), g_c2[kk[j]]);
                int k = kk[j];
                if (d2 < best || (d2 == best && k < bk)) { best = d2; bk = k; }
            }
        }
    } else {
        // overflow fallback: exact full scan (rare)
        for (int g0 = 0; g0 < KC; g0 += 4) {
            float acc[4] = {0.f, 0.f, 0.f, 0.f};
            float f2a = 0.0f;
            const float* cp = cb + (size_t)g0 * DIM;
            for (int d = 0; d < DIM; ++d) {
                float fv = zb[(size_t)d * HW + r];
                if (g0 == 0) f2a = __fadd_rn(f2a, __fmul_rn(fv, fv));
                acc[0] = __fmaf_rn(fv, cp[d], acc[0]);
                acc[1] = __fmaf_rn(fv, cp[DIM + d], acc[1]);
                acc[2] = __fmaf_rn(fv, cp[2 * DIM + d], acc[2]);
                acc[3] = __fmaf_rn(fv, cp[3 * DIM + d], acc[3]);
            }
            if (g0 == 0) f2 = f2a;
            for (int j = 0; j < 4; ++j) {
                float d2 = __fadd_rn(__fsub_rn(f2, 2.0f * acc[j]), g_c2[g0 + j]);
                int k = g0 + j;
                if (d2 < best || (d2 == best && k < bk)) { best = d2; bk = k; }
            }
        }
    }
    g_idx[n] = bk;
    atomicAdd(&g_counts[bk], 1);
}

// ===========================================================================
__global__ void __launch_bounds__(256) k_scatter(const float* __restrict__ z,
                                                 const float* __restrict__ cb,
                                                 float* __restrict__ out,
                                                 size_t osz) {
    int n  = blockIdx.x * 256 + threadIdx.x;
    int b  = n >> 10, hw = n & 1023;
    int k  = g_idx[n];
    if (OUT_IDX + (size_t)n < osz) out[OUT_IDX + n] = (float)k;

    const float*  zr   = z  + (size_t)b * DIM * HW + hw;
    float*        orow = out + OUT_ZQ + (size_t)b * DIM * HW + hw;
    const float4* cr   = (const float4*)(cb + (size_t)k * DIM);
    float*        dwr  = g_dw + (size_t)k * DIM;

    float ls = 0.0f;
#pragma unroll 4
    for (int d4 = 0; d4 < 64; ++d4) {
        float4 qv = cr[d4];
        int d = d4 * 4;
        float z0 = zr[(size_t)(d + 0) * HW];
        float z1 = zr[(size_t)(d + 1) * HW];
        float z2 = zr[(size_t)(d + 2) * HW];
        float z3 = zr[(size_t)(d + 3) * HW];
        orow[(size_t)(d + 0) * HW] = qv.x;
        orow[(size_t)(d + 1) * HW] = qv.y;
        orow[(size_t)(d + 2) * HW] = qv.z;
        orow[(size_t)(d + 3) * HW] = qv.w;
        float e0 = qv.x - z0, e1 = qv.y - z1, e2 = qv.z - z2, e3 = qv.w - z3;
        ls = fmaf(e0, e0, ls); ls = fmaf(e1, e1, ls);
        ls = fmaf(e2, e2, ls); ls = fmaf(e3, e3, ls);
        atomicAdd(&dwr[d + 0], z0);
        atomicAdd(&dwr[d + 1], z1);
        atomicAdd(&dwr[d + 2], z2);
        atomicAdd(&dwr[d + 3], z3);
    }

    for (int o = 16; o > 0; o >>= 1) ls += __shfl_down_sync(0xffffffffu, ls, o);
    __shared__ float ws[8];
    int lane = threadIdx.x & 31, w = threadIdx.x >> 5;
    if (lane == 0) ws[w] = ls;
    __syncthreads();
    if (threadIdx.x == 0) {
        float s = 0.0f;
#pragma unroll
        for (int i = 0; i < 8; ++i) s += ws[i];
        atomicAdd(&g_loss, (double)s);
    }
}

// ===========================================================================
__global__ void k_fin_a(const float* __restrict__ ema_cs,
                        float* __restrict__ out, size_t osz) {
    int k = threadIdx.x;
    float cs = __fadd_rn(__fmul_rn(0.99f, ema_cs[k]),
                         __fmul_rn(0.01f, (float)g_counts[k]));
    __shared__ float red[1024];
    red[k] = cs;
    __syncthreads();
    for (int o = 512; o > 0; o >>= 1) {
        if (k < o) red[k] += red[k + o];
        __syncthreads();
    }
    float n = red[0];
    float smv = (cs + 1e-5f) / (n + 1024.0f * 1e-5f) * n;
    g_smooth[k] = smv;
    int dead = cs < 1.0f;
    g_dead[k] = dead;
    if (OUT_CS + (size_t)k < osz) out[OUT_CS + k] = dead ? 1.0f : cs;
    if (k == 0 && OUT_LOSS < osz)
        out[OUT_LOSS] = (float)(0.5 * g_loss / 16777216.0);
}

// ===========================================================================
__global__ void k_fin_b(const float* __restrict__ ema_dw,
                        const float* __restrict__ z,
                        float* __restrict__ out, size_t osz) {
    int k = blockIdx.x;
    int d = threadIdx.x;
    size_t e = (size_t)k * DIM + d;
    float dwe = __fadd_rn(__fmul_rn(0.99f, ema_dw[e]),
                          __fmul_rn(0.01f, g_dw[e]));
    float cbv = dwe / g_smooth[k];
    if (g_dead[k]) {
        int r = g_rand[k];
        int rb = r >> 10, rhw = r & 1023;
        float rr = z[((size_t)rb * DIM + d) * HW + rhw];
        cbv = rr;
        dwe = rr;
    }
    if (OUT_CB + e < osz) out[OUT_CB + e] = cbv;
    if (OUT_DW + e < osz) out[OUT_DW + e] = dwe;
}

// ===========================================================================
extern "C" void kernel_launch(void* const* d_in, const int* in_sizes, int n_in,
                              void* d_out, int out_size) {
    const float* z      = (const float*)d_in[0];
    const float* cb     = (const float*)d_in[1];
    const float* ema_cs = (const float*)d_in[2];
    const float* ema_dw = (const float*)d_in[3];
    float* out = (float*)d_out;
    size_t osz = (size_t)out_size;

    cudaFuncSetAttribute(k_filter, cudaFuncAttributeMaxDynamicSharedMemorySize,
                         SMEM_FILT);

    k_init<<<1024, 256>>>();
    k_c2<<<4, 256>>>(cb);
    k_rng<<<1, 512>>>();
    k_filter<<<2048, 256, SMEM_FILT>>>(z, cb);
    k_cand<<<2048, 256>>>();
    k_exact<<<256, 256>>>(z, cb);
    k_scatter<<<256, 256>>>(z, cb, out, osz);
    k_fin_a<<<1, 1024>>>(ema_cs, out, osz);
    k_fin_b<<<1024, 256>>>(ema_dw, z, out, osz);
}

// round 7
// speedup vs baseline: 2.1761x; 1.9777x over previous
#include <cuda_runtime.h>
#include <cuda_fp16.h>
#include <cstdint>
#include <cstddef>

// Problem constants
#define NROWS 65536   // 64*32*32 flat rows
#define KC    1024    // codes
#define DIM   256     // embedding dim
#define HW    1024    // 32*32

// Output packing (tuple order, all float32)
#define OUT_ZQ   0ull
#define OUT_LOSS 16777216ull
#define OUT_IDX  16777217ull
#define OUT_CB   16842753ull
#define OUT_CS   17104897ull
#define OUT_DW   17105921ull

#define NSLOT  48
#define MARGIN 1.2e-2f

// Scratch (device globals: no allocations allowed)
__device__ float   g_c2[KC];
__device__ int     g_idx[NROWS];
__device__ int     g_counts[KC];
__device__ float   g_dw[KC * DIM];
__device__ double  g_loss;
__device__ int     g_rand[KC];
__device__ float   g_smooth[KC];
__device__ int     g_dead[KC];
__device__ int     g_ccnt[NROWS];
__device__ int     g_cand[NROWS * NSLOT];
__device__ __half2 g_cbh[16 * 128 * 64];   // codebook, tile-major half2 layout

// ===========================================================================
#define CP_ASYNC16(dst, src) \
    asm volatile("cp.async.ca.shared.global [%0], [%1], 16;" :: "r"(dst), "l"(src))
#define CP_COMMIT()  asm volatile("cp.async.commit_group;" ::: "memory")
#define CP_WAIT0()   asm volatile("cp.async.wait_group 0;" ::: "memory")

__device__ __forceinline__ uint32_t smem_to_u32(const void* p) {
    uint32_t a;
    asm("{ .reg .u64 t; cvta.to.shared.u64 t, %1; cvt.u32.u64 %0, t; }"
        : "=r"(a) : "l"(p));
    return a;
}

// ===========================================================================
__global__ void k_init() {
    int i = blockIdx.x * blockDim.x + threadIdx.x;   // 262144
    if (i < KC * DIM) g_dw[i] = 0.0f;
    if (i < KC)       g_counts[i] = 0;
    if (i < NROWS)    g_ccnt[i] = 0;
    if (i == 0)       g_loss = 0.0;
}

// c2[k] = sum_d fl(cb[k][d]^2), sequential in-order fp32 (XLA CPU naive reduce)
__global__ void k_c2(const float* __restrict__ cb) {
    int k = blockIdx.x * blockDim.x + threadIdx.x;
    if (k >= KC) return;
    const float* row = cb + (size_t)k * DIM;
    float s = 0.0f;
    for (int d = 0; d < DIM; ++d) {
        float v = row[d];
        s = __fadd_rn(s, __fmul_rn(v, v));
    }
    g_c2[k] = s;
}

// Codebook -> half2 tile layout: g_cbh[t*8192 + d2*64 + code] = (c[2d2], c[2d2+1])
__global__ void k_cbt(const float* __restrict__ cb) {
    int idx = blockIdx.x * 256 + threadIdx.x;        // 512 blocks -> 131072
    int t = idx >> 13, rem = idx & 8191;
    int d2 = rem >> 6, code = rem & 63;
    const float* src = cb + (size_t)(t * 64 + code) * DIM + 2 * d2;
    g_cbh[idx] = __floats2half2_rn(src[0], src[1]);
}

// Exact JAX threefry2x32 for key(1)
__device__ __forceinline__ uint32_t tf_rotl(uint32_t v, int r) {
    return (v << r) | (v >> (32 - r));
}
__global__ void k_rng() {
    int i = threadIdx.x;
    if (i >= 512) return;
    const uint32_t ks0 = 0u, ks1 = 1u, ks2 = 0x1BD11BDBu;
    uint32_t x0 = (uint32_t)i + ks0;
    uint32_t x1 = (uint32_t)(i + 512) + ks1;
    const int ra[4] = {13, 15, 26, 6};
    const int rb[4] = {17, 29, 16, 24};
#define TF_R4(rots) { x0 += x1; x1 = tf_rotl(x1, rots[0]); x1 ^= x0; \
                      x0 += x1; x1 = tf_rotl(x1, rots[1]); x1 ^= x0; \
                      x0 += x1; x1 = tf_rotl(x1, rots[2]); x1 ^= x0; \
                      x0 += x1; x1 = tf_rotl(x1, rots[3]); x1 ^= x0; }
    TF_R4(ra); x0 += ks1; x1 += ks2 + 1u;
    TF_R4(rb); x0 += ks2; x1 += ks0 + 2u;
    TF_R4(ra); x0 += ks0; x1 += ks1 + 3u;
    TF_R4(rb); x0 += ks1; x1 += ks2 + 4u;
    TF_R4(ra); x0 += ks2; x1 += ks0 + 5u;
#undef TF_R4
    g_rand[i]       = (int)(x0 & 0xFFFFu);
    g_rand[i + 512] = (int)(x1 & 0xFFFFu);
}

// ===========================================================================
// k_filter: fp16 HFMA2 approx GEMM + fused candidate collection.
// CTA = 32 rows, 256 threads, 2048 CTAs.
// smem bytes:
//   s_flat h2[128 d2][32 r]     @0       16384
//   s_code h2[128 d2][72] x2    @16384   73728   (stride 72, 64 used; dbl buf)
//   s_c2   float[1024]          @90112    4096
//   s_rmin float[32]            @94208     128
#define OFF_CODE0 16384
#define OFF_CODE1 53248
#define OFF_C2F   90112
#define OFF_RMIN  94208
#define SMEM_FILT 94336

__global__ void __launch_bounds__(256) k_filter(const float* __restrict__ z) {
    extern __shared__ char smraw[];
    __half*  s_flat_h  = (__half*)smraw;
    __half2* s_flat_h2 = (__half2*)smraw;
    float*   s_c2      = (float*)(smraw + OFF_C2F);
    float*   s_rmin    = (float*)(smraw + OFF_RMIN);
    const uint32_t uS = smem_to_u32(smraw);

    const int tid = threadIdx.x;
    const int g = tid & 15;        // code-group: codes 4g..4g+3 of tile
    const int q = tid >> 4;        // row-group : rows 2q, 2q+1

    for (int i = tid; i < KC; i += 256) s_c2[i] = g_c2[i];

    const int n0 = blockIdx.x * 32;
    const int b = n0 >> 10, hw0 = n0 & 1023;
    const float* zb = z + (size_t)b * (DIM * HW) + hw0;

    // ---- stage flat tile: half at [d2][r*2 + (d&1)]
    {
        int r = tid & 31, dchunk = tid >> 5;         // 8 chunks x 32 dims
#pragma unroll
        for (int i = 0; i < 32; ++i) {
            int d = dchunk * 32 + i;
            float v = zb[(size_t)d * HW + r];
            s_flat_h[(d >> 1) * 64 + r * 2 + (d & 1)] = __float2half(v);
        }
    }

    // ---- prologue: stage code tile 0 via cp.async
    {
        const __half2* srcb = g_cbh;
#pragma unroll
        for (int i = 0; i < 8; ++i) {
            int cidx = tid + 256 * i;                // 2048 chunks of 16B
            int d2 = cidx >> 4, seg = cidx & 15;
            CP_ASYNC16(uS + OFF_CODE0 + (uint32_t)(d2 * 288 + seg * 16),
                       srcb + d2 * 64 + seg * 4);
        }
        CP_COMMIT();
    }

    float sc[2][64];
    float runmin0 = 3.4e38f, runmin1 = 3.4e38f;

#pragma unroll
    for (int t = 0; t < 16; ++t) {
        CP_WAIT0();
        __syncthreads();
        if (t < 15) {   // stage next tile into other buffer
            const __half2* srcb = g_cbh + (t + 1) * 8192;
            uint32_t dstb = uS + (((t + 1) & 1) ? OFF_CODE1 : OFF_CODE0);
#pragma unroll
            for (int i = 0; i < 8; ++i) {
                int cidx = tid + 256 * i;
                int d2 = cidx >> 4, seg = cidx & 15;
                CP_ASYNC16(dstb + (uint32_t)(d2 * 288 + seg * 16),
                           srcb + d2 * 64 + seg * 4);
            }
            CP_COMMIT();
        }

        const __half2* s_code_h2 =
            (__half2*)(smraw + ((t & 1) ? OFF_CODE1 : OFF_CODE0));

        float facc[2][4];
#pragma unroll
        for (int a = 0; a < 2; ++a)
#pragma unroll
            for (int c = 0; c < 4; ++c) facc[a][c] = 0.0f;

        // 4 chunks of 32 d2 (64 dims): h2 accumulate, flush to fp32 (= R6 numerics)
        for (int ch = 0; ch < 4; ++ch) {
            __half2 acc[2][4];
#pragma unroll
            for (int a = 0; a < 2; ++a)
#pragma unroll
                for (int c = 0; c < 4; ++c) acc[a][c] = __float2half2_rn(0.0f);
#pragma unroll 8
            for (int i = 0; i < 32; ++i) {
                int d2 = ch * 32 + i;
                float2 faf = *(const float2*)(s_flat_h2 + d2 * 32 + 2 * q);
                float4 ccf = *(const float4*)(s_code_h2 + d2 * 72 + 4 * g);
                __half2 fa0 = *(__half2*)&faf.x;
                __half2 fa1 = *(__half2*)&faf.y;
                __half2 c0 = *(__half2*)&ccf.x;
                __half2 c1 = *(__half2*)&ccf.y;
                __half2 c2v = *(__half2*)&ccf.z;
                __half2 c3 = *(__half2*)&ccf.w;
                acc[0][0] = __hfma2(fa0, c0, acc[0][0]);
                acc[0][1] = __hfma2(fa0, c1, acc[0][1]);
                acc[0][2] = __hfma2(fa0, c2v, acc[0][2]);
                acc[0][3] = __hfma2(fa0, c3, acc[0][3]);
                acc[1][0] = __hfma2(fa1, c0, acc[1][0]);
                acc[1][1] = __hfma2(fa1, c1, acc[1][1]);
                acc[1][2] = __hfma2(fa1, c2v, acc[1][2]);
                acc[1][3] = __hfma2(fa1, c3, acc[1][3]);
            }
#pragma unroll
            for (int a = 0; a < 2; ++a)
#pragma unroll
                for (int c = 0; c < 4; ++c) {
                    float2 tv = __half22float2(acc[a][c]);
                    facc[a][c] += tv.x + tv.y;
                }
        }

        // ---- epilogue: s = c2[k] - 2*dot ; keep in regs; track min
        int kb = t * 64 + 4 * g;
#pragma unroll
        for (int a = 0; a < 2; ++a) {
            float s0 = fmaf(-2.0f, facc[a][0], s_c2[kb + 0]);
            float s1 = fmaf(-2.0f, facc[a][1], s_c2[kb + 1]);
            float s2 = fmaf(-2.0f, facc[a][2], s_c2[kb + 2]);
            float s3 = fmaf(-2.0f, facc[a][3], s_c2[kb + 3]);
            sc[a][t * 4 + 0] = s0; sc[a][t * 4 + 1] = s1;
            sc[a][t * 4 + 2] = s2; sc[a][t * 4 + 3] = s3;
            float m = fminf(fminf(s0, s1), fminf(s2, s3));
            if (a == 0) runmin0 = fminf(runmin0, m);
            else        runmin1 = fminf(runmin1, m);
        }
    }

    // ---- row min across the 16 g-lanes (xor offsets < 16 stay in half-warp)
#pragma unroll
    for (int off = 1; off < 16; off <<= 1) {
        runmin0 = fminf(runmin0, __shfl_xor_sync(0xffffffffu, runmin0, off));
        runmin1 = fminf(runmin1, __shfl_xor_sync(0xffffffffu, runmin1, off));
    }
    if (g == 0) { s_rmin[2 * q] = runmin0; s_rmin[2 * q + 1] = runmin1; }
    __syncthreads();

    // ---- fused candidate collection (direct global atomics, ~8/row total)
#pragma unroll
    for (int a = 0; a < 2; ++a) {
        int row = n0 + 2 * q + a;
        float thr = s_rmin[2 * q + a] + MARGIN;
#pragma unroll
        for (int j = 0; j < 64; ++j) {
            if (sc[a][j] <= thr) {
                int k = (j >> 2) * 64 + 4 * g + (j & 3);
                int p = atomicAdd(&g_ccnt[row], 1);
                if (p < NSLOT) g_cand[row * NSLOT + p] = k;
            }
        }
    }
}

// ===========================================================================
// k_exact: warp per row; lane per candidate. Bitwise sequential fp32 chains;
// tie -> lowest k. 8192 blocks x 256 threads.
__global__ void __launch_bounds__(256) k_exact(const float* __restrict__ z,
                                               const float* __restrict__ cb) {
    int wid = threadIdx.x >> 5, lane = threadIdx.x & 31;
    int row = blockIdx.x * 8 + wid;
    int b = row >> 10, r = row & 1023;
    const float* zb = z + (size_t)b * (DIM * HW);
    int cN = g_ccnt[row];

    float best = 3.4e38f; int bk = 1 << 30;
    float f2 = 0.0f;

    if (cN <= NSLOT) {
        for (int pass = 0; pass * 32 < cN; ++pass) {
            int idx = pass * 32 + lane;
            int active = idx < cN;
            int k = active ? g_cand[row * NSLOT + idx] : 0;
            const float* ck = cb + (size_t)k * DIM;
            float acc = 0.0f, f2a = 0.0f;
#pragma unroll 8
            for (int d = 0; d < DIM; ++d) {
                float fv = zb[(size_t)d * HW + r];      // broadcast
                if (pass == 0) f2a = __fadd_rn(f2a, __fmul_rn(fv, fv));
                acc = __fmaf_rn(fv, ck[d], acc);
            }
            if (pass == 0) f2 = f2a;
            if (active) {
                float d2 = __fadd_rn(__fsub_rn(f2, 2.0f * acc), g_c2[k]);
                if (d2 < best || (d2 == best && k < bk)) { best = d2; bk = k; }
            }
        }
    } else {
        // overflow fallback: exact full scan, codes lane, lane+32, ...
        for (int g0 = 0; g0 < KC; g0 += 32) {
            int k = g0 + lane;
            const float* ck = cb + (size_t)k * DIM;
            float acc = 0.0f, f2a = 0.0f;
#pragma unroll 8
            for (int d = 0; d < DIM; ++d) {
                float fv = zb[(size_t)d * HW + r];
                if (g0 == 0) f2a = __fadd_rn(f2a, __fmul_rn(fv, fv));
                acc = __fmaf_rn(fv, ck[d], acc);
            }
            if (g0 == 0) f2 = f2a;
            float d2 = __fadd_rn(__fsub_rn(f2, 2.0f * acc), g_c2[k]);
            if (d2 < best || (d2 == best && k < bk)) { best = d2; bk = k; }
        }
    }

    // warp reduce: min value, tie -> lowest k
#pragma unroll
    for (int off = 16; off > 0; off >>= 1) {
        float ov = __shfl_xor_sync(0xffffffffu, best, off);
        int   ok = __shfl_xor_sync(0xffffffffu, bk,   off);
        if (ov < best || (ov == best && ok < bk)) { best = ov; bk = ok; }
    }
    if (lane == 0) {
        g_idx[row] = bk;
        atomicAdd(&g_counts[bk], 1);
    }
}

// ===========================================================================
__global__ void __launch_bounds__(256) k_scatter(const float* __restrict__ z,
                                                 const float* __restrict__ cb,
                                                 float* __restrict__ out,
                                                 size_t osz) {
    int n  = blockIdx.x * 256 + threadIdx.x;
    int b  = n >> 10, hw = n & 1023;
    int k  = g_idx[n];
    if (OUT_IDX + (size_t)n < osz) out[OUT_IDX + n] = (float)k;

    const float*  zr   = z  + (size_t)b * DIM * HW + hw;
    float*        orow = out + OUT_ZQ + (size_t)b * DIM * HW + hw;
    const float4* cr   = (const float4*)(cb + (size_t)k * DIM);
    float*        dwr  = g_dw + (size_t)k * DIM;

    float ls = 0.0f;
#pragma unroll 4
    for (int d4 = 0; d4 < 64; ++d4) {
        float4 qv = cr[d4];
        int d = d4 * 4;
        float z0 = zr[(size_t)(d + 0) * HW];
        float z1 = zr[(size_t)(d + 1) * HW];
        float z2 = zr[(size_t)(d + 2) * HW];
        float z3 = zr[(size_t)(d + 3) * HW];
        orow[(size_t)(d + 0) * HW] = qv.x;
        orow[(size_t)(d + 1) * HW] = qv.y;
        orow[(size_t)(d + 2) * HW] = qv.z;
        orow[(size_t)(d + 3) * HW] = qv.w;
        float e0 = qv.x - z0, e1 = qv.y - z1, e2 = qv.z - z2, e3 = qv.w - z3;
        ls = fmaf(e0, e0, ls); ls = fmaf(e1, e1, ls);
        ls = fmaf(e2, e2, ls); ls = fmaf(e3, e3, ls);
        atomicAdd(&dwr[d + 0], z0);
        atomicAdd(&dwr[d + 1], z1);
        atomicAdd(&dwr[d + 2], z2);
        atomicAdd(&dwr[d + 3], z3);
    }

    for (int o = 16; o > 0; o >>= 1) ls += __shfl_down_sync(0xffffffffu, ls, o);
    __shared__ float ws[8];
    int lane = threadIdx.x & 31, w = threadIdx.x >> 5;
    if (lane == 0) ws[w] = ls;
    __syncthreads();
    if (threadIdx.x == 0) {
        float s = 0.0f;
#pragma unroll
        for (int i = 0; i < 8; ++i) s += ws[i];
        atomicAdd(&g_loss, (double)s);
    }
}

// ===========================================================================
__global__ void k_fin_a(const float* __restrict__ ema_cs,
                        float* __restrict__ out, size_t osz) {
    int k = threadIdx.x;
    float cs = __fadd_rn(__fmul_rn(0.99f, ema_cs[k]),
                         __fmul_rn(0.01f, (float)g_counts[k]));
    __shared__ float red[1024];
    red[k] = cs;
    __syncthreads();
    for (int o = 512; o > 0; o >>= 1) {
        if (k < o) red[k] += red[k + o];
        __syncthreads();
    }
    float n = red[0];
    float smv = (cs + 1e-5f) / (n + 1024.0f * 1e-5f) * n;
    g_smooth[k] = smv;
    int dead = cs < 1.0f;
    g_dead[k] = dead;
    if (OUT_CS + (size_t)k < osz) out[OUT_CS + k] = dead ? 1.0f : cs;
    if (k == 0 && OUT_LOSS < osz)
        out[OUT_LOSS] = (float)(0.5 * g_loss / 16777216.0);
}

// ===========================================================================
__global__ void k_fin_b(const float* __restrict__ ema_dw,
                        const float* __restrict__ z,
                        float* __restrict__ out, size_t osz) {
    int k = blockIdx.x;
    int d = threadIdx.x;
    size_t e = (size_t)k * DIM + d;
    float dwe = __fadd_rn(__fmul_rn(0.99f, ema_dw[e]),
                          __fmul_rn(0.01f, g_dw[e]));
    float cbv = dwe / g_smooth[k];
    if (g_dead[k]) {
        int r = g_rand[k];
        int rb = r >> 10, rhw = r & 1023;
        float rr = z[((size_t)rb * DIM + d) * HW + rhw];
        cbv = rr;
        dwe = rr;
    }
    if (OUT_CB + e < osz) out[OUT_CB + e] = cbv;
    if (OUT_DW + e < osz) out[OUT_DW + e] = dwe;
}

// ===========================================================================
extern "C" void kernel_launch(void* const* d_in, const int* in_sizes, int n_in,
                              void* d_out, int out_size) {
    const float* z      = (const float*)d_in[0];
    const float* cb     = (const float*)d_in[1];
    const float* ema_cs = (const float*)d_in[2];
    const float* ema_dw = (const float*)d_in[3];
    float* out = (float*)d_out;
    size_t osz = (size_t)out_size;

    cudaFuncSetAttribute(k_filter, cudaFuncAttributeMaxDynamicSharedMemorySize,
                         SMEM_FILT);

    k_init<<<1024, 256>>>();
    k_c2<<<4, 256>>>(cb);
    k_cbt<<<512, 256>>>(cb);
    k_rng<<<1, 512>>>();
    k_filter<<<2048, 256, SMEM_FILT>>>(z);
    k_exact<<<8192, 256>>>(z, cb);
    k_scatter<<<256, 256>>>(z, cb, out, osz);
    k_fin_a<<<1, 1024>>>(ema_cs, out, osz);
    k_fin_b<<<1024, 256>>>(ema_dw, z, out, osz);
}